// round 17
// baseline (speedup 1.0000x reference)
#include <cuda_runtime.h>
#include <cuda_fp16.h>
#include <cstdint>
#include <math_constants.h>

#define BATCH 4
#define SEQ   2048
#define DIM   1024
#define MQ    (BATCH * SEQ)   // 8192

// ---------------------------------------------------------------------------
// Persistent scratch (device globals — allocation-free per harness rules)
// ---------------------------------------------------------------------------
__device__ half  g_xh[(long)MQ * DIM];
__device__ half  g_Wh[3][(long)DIM * DIM];
__device__ half  g_QKV[3][(long)MQ * DIM];
__device__ float g_S[(long)BATCH * SEQ * SEQ];
__device__ half  g_Ph[(long)BATCH * SEQ * SEQ];

// work queue + fine-grained dependency counters (zero-init; self-reset at exit)
__device__ unsigned g_qnext;
__device__ unsigned g_exit;
__device__ unsigned g_cxc[64];        // x cast per 128-row m-block (4 tiles)
__device__ unsigned g_cwc[3][8];      // W cast per (zsel, n-block) (4 tiles)
__device__ unsigned g_cq[64];         // Q proj per m-block (8 n-tiles)
__device__ unsigned g_ck[64];         // K proj per m-block
__device__ unsigned g_cv[BATCH];      // V proj per batch (128 tiles)
__device__ unsigned g_csc[BATCH][16]; // scores per (bz, m-block) (16 n-tiles)
__device__ unsigned g_csm[BATCH][16]; // softmax per (bz, m-block) (16 items)

// Queue layout (dependency order):
//   [0,256)        x-cast (32 rows each)
//   [256,352)      W-cast (32 rows each; 32 per W)
//   [352,1888)     proj: Q(512) K(512) V(512)
//   [1888,2912)    scores
//   [2912,3936)    softmax items (8 rows each, warp-per-row)
//   [3936,4448)    AV
#define T_XC_END   256
#define T_WC_END   352
#define T_PROJ_END 1888
#define T_SC_END   2912
#define T_SM_END   3936
#define T_TOTAL    4448

// ---------------------------------------------------------------------------
// helpers
// ---------------------------------------------------------------------------
__device__ __forceinline__ uint32_t smem_u32(const void* p) {
    uint32_t a;
    asm("{ .reg .u64 t; cvta.to.shared.u64 t, %1; cvt.u32.u64 %0, t; }" : "=r"(a) : "l"(p));
    return a;
}
__device__ __forceinline__ void cp16(uint32_t dst, const void* src) {
    asm volatile("cp.async.cg.shared.global [%0], [%1], 16;" :: "r"(dst), "l"(src));
}
__device__ __forceinline__ void cp_commit() {
    asm volatile("cp.async.commit_group;" ::: "memory");
}
__device__ __forceinline__ void cp_wait2() {
    asm volatile("cp.async.wait_group 2;" ::: "memory");
}
__device__ __forceinline__ void cp_wait0() {
    asm volatile("cp.async.wait_group 0;" ::: "memory");
}
__device__ __forceinline__ void ldsm4(uint32_t r[4], uint32_t addr) {
    asm volatile("ldmatrix.sync.aligned.m8n8.x4.shared.b16 {%0,%1,%2,%3}, [%4];"
                 : "=r"(r[0]), "=r"(r[1]), "=r"(r[2]), "=r"(r[3]) : "r"(addr));
}
__device__ __forceinline__ void ldsm4t(uint32_t r[4], uint32_t addr) {
    asm volatile("ldmatrix.sync.aligned.m8n8.x4.trans.shared.b16 {%0,%1,%2,%3}, [%4];"
                 : "=r"(r[0]), "=r"(r[1]), "=r"(r[2]), "=r"(r[3]) : "r"(addr));
}
__device__ __forceinline__ void mma16816(float c[4], const uint32_t a[4],
                                         uint32_t b0, uint32_t b1) {
    asm volatile(
        "mma.sync.aligned.m16n8k16.row.col.f32.f16.f16.f32 "
        "{%0,%1,%2,%3}, {%4,%5,%6,%7}, {%8,%9}, {%0,%1,%2,%3};"
        : "+f"(c[0]), "+f"(c[1]), "+f"(c[2]), "+f"(c[3])
        : "r"(a[0]), "r"(a[1]), "r"(a[2]), "r"(a[3]), "r"(b0), "r"(b1));
}
__device__ __forceinline__ unsigned ld_acq(const unsigned* p) {
    unsigned v;
    asm volatile("ld.acquire.gpu.u32 %0, [%1];" : "=r"(v) : "l"(p) : "memory");
    return v;
}
__device__ __forceinline__ void spin_ge(const unsigned* p, unsigned tgt) {
    int it = 0;
    while (ld_acq(p) < tgt) {
        __nanosleep(64);
        if (++it > 8000000) break;   // safety valve: fail, don't hang
    }
}

// ---------------------------------------------------------------------------
// cast tile: convert 32768 fp32 -> fp16 (32 rows of 1024)
// ---------------------------------------------------------------------------
__device__ __forceinline__ void cast_tile(const float* __restrict__ s,
                                          half* __restrict__ d, long base)
{
    const float4* s4 = (const float4*)(s) + base;
    half2* d2 = (half2*)(d) + base * 2;
    const int tid = threadIdx.x;
    #pragma unroll 4
    for (int it = 0; it < 32; it++) {
        const int i = it * 256 + tid;
        float4 v = s4[i];
        half2 a; a.x = __float2half(v.x); a.y = __float2half(v.y);
        half2 b; b.x = __float2half(v.z); b.y = __float2half(v.w);
        d2[2 * i] = a;
        d2[2 * i + 1] = b;
    }
}

// ---------------------------------------------------------------------------
// GEMM tile body: 4-stage cp.async(16B,.cg) pipeline, depth-3 prefetch.
// Math identical to the 464us build.
// ---------------------------------------------------------------------------
#define LDA    40
#define LDBNN  136
#define STAGES 4

#define A_TILE_B   (128 * LDA * 2)          // 10240
#define BNT_TILE_B (128 * LDA * 2)          // 10240
#define BNN_TILE_B (32 * LDBNN * 2)         // 8704
#define SMEM_MEGA  (STAGES * (A_TILE_B + BNT_TILE_B))   // 81920

template <bool BKMAJOR, int MODE>
__device__ __forceinline__ void gemm_body(
    char* smem,
    const half* __restrict__ A, const half* __restrict__ B,
    const float* __restrict__ bias,
    float* __restrict__ Cf, half* __restrict__ Ch,
    int N, int K, int m0, int n0, float alpha)
{
    constexpr int B_TILE_B = BKMAJOR ? BNT_TILE_B : BNN_TILE_B;
    constexpr int OFF_B    = A_TILE_B;
    constexpr int STAGE_B  = A_TILE_B + B_TILE_B;

    const uint32_t sb = smem_u32(smem);
    const int tid = threadIdx.x;
    const int lane = tid & 31;
    const int wid = tid >> 5;
    const int wm = wid >> 2;
    const int wn = wid & 3;

    float c[4][4][4];
    #pragma unroll
    for (int i = 0; i < 4; i++)
        #pragma unroll
        for (int j = 0; j < 4; j++)
            #pragma unroll
            for (int r = 0; r < 4; r++) c[i][j][r] = 0.f;

    // one 32-K slab -> stage st, 16B cp.async.cg chunks
    auto issue_stage = [&](int st, int k0) {
        const uint32_t s0 = sb + st * STAGE_B;
        // A tile: 128 rows x 4 chunks of 16B = 512 chunks, 2/thread
        #pragma unroll
        for (int i = 0; i < 2; i++) {
            const int q = i * 256 + tid;
            const int r = q >> 2, ch = q & 3;
            cp16(s0 + r * 80 + ch * 16, A + (long)(m0 + r) * K + k0 + ch * 8);
        }
        if (BKMAJOR) {
            #pragma unroll
            for (int i = 0; i < 2; i++) {
                const int q = i * 256 + tid;
                const int r = q >> 2, ch = q & 3;
                cp16(s0 + OFF_B + r * 80 + ch * 16, B + (long)(n0 + r) * K + k0 + ch * 8);
            }
        } else {
            // B: 32 rows x 16 chunks of 16B = 512 chunks, 2/thread
            #pragma unroll
            for (int i = 0; i < 2; i++) {
                const int q = i * 256 + tid;
                const int r = q >> 4, ch = q & 15;
                cp16(s0 + OFF_B + r * 272 + ch * 16, B + (long)(k0 + r) * N + n0 + ch * 8);
            }
        }
        cp_commit();
    };

    const int NIT = K >> 5;      // >= 32 always
    issue_stage(0, 0);
    issue_stage(1, 32);
    issue_stage(2, 64);

    int st = 0;
    for (int it = 0; it < NIT; it++) {
        cp_wait2();
        __syncthreads();
        if (it + 3 < NIT) issue_stage((st + 3) & 3, (it + 3) * 32);

        const half* tA = (const half*)(smem + st * STAGE_B);
        const half* tB = (const half*)(smem + st * STAGE_B + OFF_B);

        #pragma unroll
        for (int ks = 0; ks < 2; ks++) {
            const int kk = ks * 16;
            uint32_t fa[4][4], fb[2][4];
            #pragma unroll
            for (int mf = 0; mf < 4; mf++) {
                const int row = wm * 64 + mf * 16 + (lane & 15);
                const int col = kk + (lane >> 4) * 8;
                ldsm4(fa[mf], smem_u32(&tA[row * LDA + col]));
            }
            if (BKMAJOR) {
                #pragma unroll
                for (int q = 0; q < 2; q++) {
                    const int row = wn * 32 + q * 16 + (lane & 15);
                    const int col = kk + (lane >> 4) * 8;
                    ldsm4(fb[q], smem_u32(&tB[row * LDA + col]));
                }
            } else {
                #pragma unroll
                for (int q = 0; q < 2; q++) {
                    const int row = kk + (lane >> 4) * 8 + (lane & 7);
                    const int col = wn * 32 + q * 16 + ((lane >> 3) & 1) * 8;
                    ldsm4t(fb[q], smem_u32(&tB[row * LDBNN + col]));
                }
            }
            #pragma unroll
            for (int mf = 0; mf < 4; mf++)
                #pragma unroll
                for (int nf = 0; nf < 4; nf++) {
                    const int q = nf >> 1, g = nf & 1;
                    mma16816(c[mf][nf], fa[mf], fb[q][g], fb[q][g + 2]);
                }
        }
        st = (st + 1) & 3;
    }
    cp_wait0();

    #pragma unroll
    for (int mf = 0; mf < 4; mf++) {
        const int m_lo = m0 + wm * 64 + mf * 16 + (lane >> 2);
        #pragma unroll
        for (int nf = 0; nf < 4; nf++) {
            const int n = n0 + wn * 32 + nf * 8 + (lane & 3) * 2;
            if (MODE == 1) {
                const float v0 = bias[n], v1 = bias[n + 1];
                __half2 h0; h0.x = __float2half(c[mf][nf][0] + v0);
                h0.y = __float2half(c[mf][nf][1] + v1);
                __half2 h1; h1.x = __float2half(c[mf][nf][2] + v0);
                h1.y = __float2half(c[mf][nf][3] + v1);
                *(__half2*)(Ch + (long)m_lo * N + n) = h0;
                *(__half2*)(Ch + (long)(m_lo + 8) * N + n) = h1;
            } else {
                float2 v0 = make_float2(c[mf][nf][0] * alpha, c[mf][nf][1] * alpha);
                float2 v1 = make_float2(c[mf][nf][2] * alpha, c[mf][nf][3] * alpha);
                *(float2*)(Cf + (long)m_lo * N + n) = v0;
                *(float2*)(Cf + (long)(m_lo + 8) * N + n) = v1;
            }
        }
    }
}

// ---------------------------------------------------------------------------
// Softmax item: 8 rows, warp w handles row base+w autonomously.
// ---------------------------------------------------------------------------
__device__ __forceinline__ void softmax_item8(long base)
{
    const int lane = threadIdx.x & 31;
    const int w = threadIdx.x >> 5;            // 0..7
    const long row = base + w;
    const float4* p4 = (const float4*)(g_S + row * SEQ);
    half* ph = g_Ph + row * SEQ;

    float m = -CUDART_INF_F, s = 0.f;
    #pragma unroll
    for (int i = 0; i < 16; i++) {
        float4 v = p4[i * 32 + lane];
        float vm = fmaxf(fmaxf(v.x, v.y), fmaxf(v.z, v.w));
        float nm = fmaxf(m, vm);
        s = s * __expf(m - nm)
          + __expf(v.x - nm) + __expf(v.y - nm)
          + __expf(v.z - nm) + __expf(v.w - nm);
        m = nm;
    }
    #pragma unroll
    for (int o = 16; o; o >>= 1) {
        float om = __shfl_xor_sync(0xffffffffu, m, o);
        float os = __shfl_xor_sync(0xffffffffu, s, o);
        float nm = fmaxf(m, om);
        s = s * __expf(m - nm) + os * __expf(om - nm);
        m = nm;
    }
    const float inv = 1.f / s;

    #pragma unroll
    for (int i = 0; i < 16; i++) {
        float4 v = p4[i * 32 + lane];
        __half2 a, b;
        a.x = __float2half(__expf(v.x - m) * inv);
        a.y = __float2half(__expf(v.y - m) * inv);
        b.x = __float2half(__expf(v.z - m) * inv);
        b.y = __float2half(__expf(v.w - m) * inv);
        uint2 pk;
        pk.x = *(uint32_t*)&a;
        pk.y = *(uint32_t*)&b;
        ((uint2*)ph)[i * 32 + lane] = pk;
    }
}

// ---------------------------------------------------------------------------
// Persistent mega-kernel: casts + GEMMs + softmax in one work queue.
// ---------------------------------------------------------------------------
__global__ __launch_bounds__(256, 2)
void mega(const float* __restrict__ x,
          const float* __restrict__ Wq, const float* __restrict__ Wk,
          const float* __restrict__ Wv,
          const float* __restrict__ bq, const float* __restrict__ bk,
          const float* __restrict__ bv, float* __restrict__ out)
{
    extern __shared__ char smem[];
    __shared__ unsigned s_t;
    const int tid = threadIdx.x;

    for (;;) {
        if (tid == 0) s_t = atomicAdd(&g_qnext, 1u);
        __syncthreads();
        const unsigned t = s_t;
        if (t >= T_TOTAL) break;

        if (t < T_XC_END) {
            cast_tile(x, g_xh, (long)t * 8192);
            __threadfence();
            __syncthreads();
            if (tid == 0) atomicAdd(&g_cxc[t >> 2], 1u);
        } else if (t < T_WC_END) {
            const int j = t - T_XC_END;
            const int zsel = j >> 5;
            const int sub = j & 31;
            const float* W = (zsel == 0) ? Wq : (zsel == 1) ? Wk : Wv;
            cast_tile(W, g_Wh[zsel], (long)sub * 8192);
            __threadfence();
            __syncthreads();
            if (tid == 0) atomicAdd(&g_cwc[zsel][sub >> 2], 1u);
        } else if (t < T_PROJ_END) {
            const int tt = t - T_WC_END;
            const int zsel = tt >> 9;
            const int r = tt & 511;
            const int nblk = r & 7;
            const int mblk = r >> 3;
            if (tid == 0) {
                spin_ge(&g_cxc[mblk], 4u);
                spin_ge(&g_cwc[zsel][nblk], 4u);
            }
            __syncthreads();
            const float* bias = (zsel == 0) ? bq : (zsel == 1) ? bk : bv;
            gemm_body<true, 1>(smem, g_xh, g_Wh[zsel], bias,
                               nullptr, g_QKV[zsel], DIM, DIM,
                               mblk * 128, nblk * 128, 1.f);
            __threadfence();
            __syncthreads();
            if (tid == 0) {
                if (zsel == 0)      atomicAdd(&g_cq[mblk], 1u);
                else if (zsel == 1) atomicAdd(&g_ck[mblk], 1u);
                else                atomicAdd(&g_cv[mblk >> 4], 1u);
            }
        } else if (t < T_SC_END) {
            const int tt = t - T_PROJ_END;
            const int bz = tt >> 8;
            const int r = tt & 255;
            const int nblk = r & 15;
            const int mblk = r >> 4;
            if (tid == 0) {
                spin_ge(&g_cq[bz * 16 + mblk], 8u);
                spin_ge(&g_ck[bz * 16 + nblk], 8u);
            }
            __syncthreads();
            gemm_body<true, 2>(smem,
                               g_QKV[0] + (long)bz * SEQ * DIM,
                               g_QKV[1] + (long)bz * SEQ * DIM, nullptr,
                               g_S + (long)bz * SEQ * SEQ, nullptr,
                               SEQ, DIM, mblk * 128, nblk * 128, 0.03125f);
            __threadfence();
            __syncthreads();
            if (tid == 0) atomicAdd(&g_csc[bz][mblk], 1u);
        } else if (t < T_SM_END) {
            const long base = (long)(t - T_SC_END) * 8;
            const int bz = (int)(base >> 11);
            const int mblk = (int)(base >> 7) & 15;
            if (tid == 0) spin_ge(&g_csc[bz][mblk], 16u);
            __syncthreads();
            softmax_item8(base);
            __threadfence();
            __syncthreads();
            if (tid == 0) atomicAdd(&g_csm[bz][mblk], 1u);
        } else {
            const int tt = t - T_SM_END;
            const int bz = tt >> 7;
            const int r = tt & 127;
            const int n0 = (r & 7) * 128;
            const int mblk = r >> 3;
            if (tid == 0) {
                spin_ge(&g_csm[bz][mblk], 16u);
                spin_ge(&g_cv[bz], 128u);
            }
            __syncthreads();
            gemm_body<false, 2>(smem,
                                g_Ph + (long)bz * SEQ * SEQ,
                                g_QKV[2] + (long)bz * SEQ * DIM, nullptr,
                                out + (long)bz * SEQ * DIM, nullptr,
                                DIM, SEQ, mblk * 128, n0, 1.f);
        }
        __syncthreads();
    }

    // ---- exit: last CTA out resets all counters (replay-safe) ----
    if (tid == 0) {
        const unsigned e = atomicAdd(&g_exit, 1u);
        if (e == gridDim.x - 1) {
            g_qnext = 0; g_exit = 0;
            #pragma unroll 1
            for (int i = 0; i < 64; i++) { g_cxc[i] = 0; g_cq[i] = 0; g_ck[i] = 0; }
            #pragma unroll 1
            for (int i = 0; i < 24; i++) ((unsigned*)g_cwc)[i] = 0;
            #pragma unroll 1
            for (int i = 0; i < BATCH; i++) g_cv[i] = 0;
            #pragma unroll 1
            for (int i = 0; i < 64; i++) {
                ((unsigned*)g_csc)[i] = 0;
                ((unsigned*)g_csm)[i] = 0;
            }
            __threadfence();
        }
    }
}

// ---------------------------------------------------------------------------
// Launch
// ---------------------------------------------------------------------------
extern "C" void kernel_launch(void* const* d_in, const int* in_sizes, int n_in,
                              void* d_out, int out_size)
{
    const float* x  = (const float*)d_in[0];
    const float* Wq = (const float*)d_in[1];
    const float* bq = (const float*)d_in[2];
    const float* Wk = (const float*)d_in[3];
    const float* bk = (const float*)d_in[4];
    const float* Wv = (const float*)d_in[5];
    const float* bv = (const float*)d_in[6];
    float* out = (float*)d_out;

    cudaFuncSetAttribute(mega, cudaFuncAttributeMaxDynamicSharedMemorySize, SMEM_MEGA);

    int dev = 0, nsm = 148, nb = 2;
    cudaGetDevice(&dev);
    cudaDeviceGetAttribute(&nsm, cudaDevAttrMultiProcessorCount, dev);
    cudaOccupancyMaxActiveBlocksPerMultiprocessor(&nb, mega, 256, SMEM_MEGA);
    if (nb < 1) nb = 1;
    int grid = nsm * nb;
    if (grid > T_TOTAL) grid = T_TOTAL;

    mega<<<grid, 256, SMEM_MEGA>>>(x, Wq, Wk, Wv, bq, bk, bv, out);
}